// round 5
// baseline (speedup 1.0000x reference)
#include <cuda_runtime.h>
#include <cuda_bf16.h>
#include <math.h>

#define Bv 32
#define Hv 128
#define Wv 128
#define Cv 10
#define Kv 32
#define CH 32

#define A_ELEMS (Bv*Hv*Wv*Kv)
#define T_FEATS 17

// -------------------- scratch (static __device__, no allocs) --------------------
__device__ __align__(256) float g_r1 [Bv*Hv*Wv*CH];   // A ping buffer
__device__ __align__(256) float g_phi[Bv*Hv*Wv*CH];   // phi; later A ping buffer
__device__ __align__(256) float g_aff[Bv*Hv*Wv*4];    // 2x-scaled neighbor affinities
__device__ __align__(256) float g_A0 [Hv*Wv*Kv];      // batch-independent init assignment
__device__ __align__(256) float g_part[Bv*Hv*Kv*13];  // pooling partials per (b,h,k)

// -------------------- f32x2 packed helpers (Blackwell FFMA2) --------------------
__device__ __forceinline__ unsigned long long pack2(float lo, float hi) {
    unsigned long long r;
    asm("mov.b64 %0,{%1,%2};" : "=l"(r) : "f"(lo), "f"(hi));
    return r;
}
__device__ __forceinline__ float2 unpack2(unsigned long long v) {
    float2 r;
    asm("mov.b64 {%0,%1},%2;" : "=f"(r.x), "=f"(r.y) : "l"(v));
    return r;
}
__device__ __forceinline__ void ffma2(unsigned long long &d,
                                      unsigned long long a, unsigned long long b) {
    asm("fma.rn.f32x2 %0, %1, %2, %0;" : "+l"(d) : "l"(a), "l"(b));
}
__device__ __forceinline__ unsigned long long fma2o(unsigned long long a,
                                                    unsigned long long b,
                                                    unsigned long long c) {
    unsigned long long r;
    asm("fma.rn.f32x2 %0, %1, %2, %3;" : "=l"(r) : "l"(a), "l"(b), "l"(c));
    return r;
}
__device__ __forceinline__ unsigned long long mul2(unsigned long long a, unsigned long long b) {
    unsigned long long r;
    asm("mul.rn.f32x2 %0, %1, %2;" : "=l"(r) : "l"(a), "l"(b));
    return r;
}

// ============================================================================
// pad kernel: no-op, used to steer ncu's fixed -s 5 onto conv123
// ============================================================================
__global__ void pad_kernel() {}

// ============================================================================
// init A0 (batch independent)
// ============================================================================
__global__ __launch_bounds__(128) void initA_kernel(float* __restrict__ A0)
{
    int h = blockIdx.x, w = threadIdx.x;
    float fh = (float)h, fw = (float)w;
    float lg[Kv]; float m = -1e30f;
    #pragma unroll
    for (int k = 0; k < Kv; k++) {
        float sh = ((k >> 3) + 0.5f) * 32.f;
        float sw = ((k & 7)  + 0.5f) * 16.f;
        float dh = fh - sh, dw = fw - sw;
        lg[k] = -(dh*dh + dw*dw) * (1.f/512.f);
        m = fmaxf(m, lg[k]);
    }
    float s = 0.f;
    #pragma unroll
    for (int k = 0; k < Kv; k++) { lg[k] = __expf(lg[k] - m); s += lg[k]; }
    float inv = 1.f / s;
    float4* dst = (float4*)(A0 + (size_t)(h*Wv + w)*Kv);
    #pragma unroll
    for (int g = 0; g < 8; g++)
        dst[g] = make_float4(lg[4*g]*inv, lg[4*g+1]*inv, lg[4*g+2]*inv, lg[4*g+3]*inv);
}

// ============================================================================
// fully fused conv1 (3x3,10->32 lookup) + conv2 (3x3,32->32) + conv3 (1x1) -> phi
// ============================================================================
#define R1PITCH 343
#define OFF_W1  0
#define OFF_B1  (OFF_W1 + 9*Cv*CH)
#define OFF_W2  (OFF_B1 + 32)
#define OFF_W3  (OFF_W2 + 9*CH*CH)
#define OFF_B2  (OFF_W3 + CH*CH)
#define OFF_B3  (OFF_B2 + 32)
#define OFF_X   (OFF_B3 + 32)
#define OFF_R1  (OFF_X + 400)
#define CONV_F  (OFF_R1 + CH*R1PITCH)
#define CONV_SMEM (CONV_F * 4)

__global__ __launch_bounds__(256) void conv123_kernel(
    const int* __restrict__ X,
    const float* __restrict__ w1, const float* __restrict__ b1,
    const float* __restrict__ w2, const float* __restrict__ b2,
    const float* __restrict__ w3, const float* __restrict__ b3,
    float* __restrict__ phi)
{
    extern __shared__ float smem[];
    float* s_w1 = smem + OFF_W1;
    float* s_b1 = smem + OFF_B1;
    float* s_w2 = smem + OFF_W2;
    float* s_w3 = smem + OFF_W3;
    float* s_b2 = smem + OFF_B2;
    float* s_b3 = smem + OFF_B3;
    int*   s_x  = (int*)(smem + OFF_X);
    float* s_r1 = smem + OFF_R1;

    int b = blockIdx.x, h0 = blockIdx.y*16, w0 = blockIdx.z*16;
    int tid = threadIdx.x;

    for (int i = tid; i < 9*Cv*CH; i += 256) s_w1[i] = w1[i];
    for (int i = tid; i < 9*CH*CH; i += 256) s_w2[i] = w2[i];
    for (int i = tid; i < CH*CH;   i += 256) s_w3[i] = w3[i];
    if (tid < 32) { s_b1[tid] = b1[tid]; s_b2[tid] = b2[tid]; s_b3[tid] = b3[tid]; }

    for (int p = tid; p < 400; p += 256) {
        int ly = p / 20, lx = p % 20;
        int gh = h0 + ly - 2, gw = w0 + lx - 2;
        s_x[p] = (gh >= 0 && gh < Hv && gw >= 0 && gw < Wv) ? X[(b*Hv+gh)*Wv+gw] : -1;
    }
    __syncthreads();

    {
        int co = tid & 31, wid = tid >> 5;
        for (int p = wid; p < 18*18; p += 8) {
            int lh = p / 18, lw = p % 18;
            float acc = s_b1[co];
            #pragma unroll
            for (int dy = 0; dy < 3; dy++) {
                #pragma unroll
                for (int dx = 0; dx < 3; dx++) {
                    int c = s_x[(lh+dy)*20 + (lw+dx)];
                    if (c >= 0) acc += s_w1[((dy*3+dx)*Cv + c)*CH + co];
                }
            }
            s_r1[co*R1PITCH + lh*19 + lw] = fmaxf(acc, 0.f);
        }
    }
    __syncthreads();

    int lh = tid >> 4, lw = tid & 15;

    unsigned long long acc2[16];
    #pragma unroll
    for (int g = 0; g < 16; g++) acc2[g] = pack2(s_b2[2*g], s_b2[2*g+1]);

    #pragma unroll
    for (int pos = 0; pos < 9; pos++) {
        int dy = pos / 3, dx = pos % 3;
        const float* in_base = s_r1 + (lh+dy)*19 + (lw+dx);
        const ulonglong2* w_base = (const ulonglong2*)(s_w2 + pos*CH*CH);
        #pragma unroll 4
        for (int ci = 0; ci < CH; ci++) {
            float v = in_base[ci*R1PITCH];
            unsigned long long v2 = pack2(v, v);
            const ulonglong2* wp = w_base + ci*8;
            #pragma unroll
            for (int g = 0; g < 8; g++) {
                ulonglong2 wv = wp[g];
                ffma2(acc2[2*g],   v2, wv.x);
                ffma2(acc2[2*g+1], v2, wv.y);
            }
        }
    }

    float a[CH];
    #pragma unroll
    for (int g = 0; g < 16; g++) {
        float2 v = unpack2(acc2[g]);
        a[2*g]   = fmaxf(v.x, 0.f);
        a[2*g+1] = fmaxf(v.y, 0.f);
    }
    unsigned long long out2[16];
    #pragma unroll
    for (int g = 0; g < 16; g++) out2[g] = pack2(s_b3[2*g], s_b3[2*g+1]);
    {
        const ulonglong2* w3p = (const ulonglong2*)s_w3;
        #pragma unroll 4
        for (int ci = 0; ci < CH; ci++) {
            unsigned long long v2 = pack2(a[ci], a[ci]);
            const ulonglong2* wp = w3p + ci*8;
            #pragma unroll
            for (int g = 0; g < 8; g++) {
                ulonglong2 wv = wp[g];
                ffma2(out2[2*g],   v2, wv.x);
                ffma2(out2[2*g+1], v2, wv.y);
            }
        }
    }

    float4* dst = (float4*)(phi + (size_t)((b*Hv + h0+lh)*Wv + w0+lw)*CH);
    #pragma unroll
    for (int g = 0; g < 8; g++) {
        float2 lo = unpack2(out2[2*g]);
        float2 hi = unpack2(out2[2*g+1]);
        dst[g] = make_float4(lo.x, lo.y, hi.x, hi.y);
    }
}

// ============================================================================
// neighbor affinity, f32x2 distance math; emits 2x-scaled weights
// ============================================================================
__device__ __forceinline__ float aff_edge2(const unsigned long long c2[16],
                                           const float* __restrict__ nb,
                                           unsigned long long M1) {
    const ulonglong2* n = (const ulonglong2*)nb;
    unsigned long long acc0 = pack2(0.f, 0.f), acc1 = pack2(0.f, 0.f);
    #pragma unroll
    for (int g = 0; g < 8; g++) {
        ulonglong2 v = n[g];
        unsigned long long d0 = fma2o(v.x, M1, c2[2*g]);
        unsigned long long d1 = fma2o(v.y, M1, c2[2*g+1]);
        acc0 = fma2o(d0, d0, acc0);
        acc1 = fma2o(d1, d1, acc1);
    }
    float2 p0 = unpack2(acc0), p1 = unpack2(acc1);
    float d2 = (p0.x + p0.y) + (p1.x + p1.y);
    return 2.f * __expf(-2.f * d2);
}

__global__ __launch_bounds__(128) void aff_kernel(
    const float* __restrict__ phi, float* __restrict__ aff)
{
    int bh = blockIdx.x; int b = bh >> 7, h = bh & 127; int w = threadIdx.x;
    size_t pix = (size_t)(b*Hv + h)*Wv + w;
    unsigned long long c2[16];
    const ulonglong2* c4 = (const ulonglong2*)(phi + pix*CH);
    #pragma unroll
    for (int g = 0; g < 8; g++) {
        ulonglong2 v = c4[g];
        c2[2*g] = v.x; c2[2*g+1] = v.y;
    }
    unsigned long long M1 = pack2(-1.f, -1.f);
    float4 wd;
    wd.x = (h+1 < Hv) ? aff_edge2(c2, phi + (pix + Wv)*CH, M1) : 0.f;
    wd.y = (h   >= 1) ? aff_edge2(c2, phi + (pix - Wv)*CH, M1) : 0.f;
    wd.z = (w+1 < Wv) ? aff_edge2(c2, phi + (pix + 1 )*CH, M1) : 0.f;
    wd.w = (w   >= 1) ? aff_edge2(c2, phi + (pix - 1 )*CH, M1) : 0.f;
    ((float4*)aff)[pix] = wd;
}

// ============================================================================
// fused 2x message-pass. A tiles in smem as ulonglong2 channel-QUADS
// [q][pix]: one LDS.128 yields two f32x2 registers, no repacking.
// Fill is a direct float4 copy. beta=2 pre-folded into aff; agg<=8 so exp safe.
// ============================================================================
#define REG 20
#define REGPIX (REG*REG)           // 400
#define MP2_SMEM (2*8*REGPIX*16 + REGPIX*16)   // 102400 + 6400 = 108800 B

__global__ __launch_bounds__(512, 2) void msgpass2_kernel(
    const float* __restrict__ Ain, int bstride,
    const float* __restrict__ aff, float* __restrict__ Aout)
{
    extern __shared__ float smem[];
    ulonglong2* sA = (ulonglong2*)smem;            // [8][400]
    ulonglong2* sB = sA + 8*REGPIX;                // [8][400]
    float4*  s_aff = (float4*)(sB + 8*REGPIX);     // [400]

    int tid = threadIdx.x;
    int b   = blockIdx.z;
    int g0h = blockIdx.y*16 - 2;
    int g0w = blockIdx.x*16 - 2;

    const float* Abase = Ain + (size_t)b * bstride;

    for (int pix = tid; pix < REGPIX; pix += 512) {
        int y = pix / REG, x = pix % REG;
        int gh = g0h + y, gw = g0w + x;
        if (gh >= 0 && gh < Hv && gw >= 0 && gw < Wv) {
            const float4* src = (const float4*)(Abase + (size_t)(gh*Wv + gw)*Kv);
            float4* dstq = (float4*)sA;
            #pragma unroll
            for (int g = 0; g < 8; g++) dstq[g*REGPIX + pix] = src[g];
            s_aff[pix] = ((const float4*)aff)[(size_t)(b*Hv + gh)*Wv + gw];
        } else {
            #pragma unroll
            for (int g = 0; g < 8; g++) sA[g*REGPIX + pix] = make_ulonglong2(0ull, 0ull);
            s_aff[pix] = make_float4(0.f, 0.f, 0.f, 0.f);
        }
    }
    __syncthreads();

    // ---- pass 0: offset 1, 18x18 region, sA -> sB ----
    if (tid < 18*18) {
        int y = 1 + tid / 18, x = 1 + tid % 18;
        int pc = y*REG + x;
        float4 wd = s_aff[pc];
        unsigned long long wx = pack2(wd.x, wd.x), wy = pack2(wd.y, wd.y);
        unsigned long long wz = pack2(wd.z, wd.z), ww = pack2(wd.w, wd.w);
        float ex[Kv]; float s = 0.f;
        #pragma unroll
        for (int q = 0; q < 8; q++) {
            const ulonglong2* r = sA + q*REGPIX + pc;
            ulonglong2 up = r[REG], dn = r[-REG], rt = r[1], lf = r[-1];
            unsigned long long a0 = mul2(wx, up.x);
            ffma2(a0, wy, dn.x); ffma2(a0, wz, rt.x); ffma2(a0, ww, lf.x);
            unsigned long long a1 = mul2(wx, up.y);
            ffma2(a1, wy, dn.y); ffma2(a1, wz, rt.y); ffma2(a1, ww, lf.y);
            float2 p0 = unpack2(a0), p1 = unpack2(a1);
            float e0 = __expf(p0.x), e1 = __expf(p0.y);
            float e2 = __expf(p1.x), e3 = __expf(p1.y);
            ex[4*q]=e0; ex[4*q+1]=e1; ex[4*q+2]=e2; ex[4*q+3]=e3;
            s += (e0 + e1) + (e2 + e3);
        }
        float inv = __fdividef(1.f, s);
        #pragma unroll
        for (int q = 0; q < 8; q++)
            sB[q*REGPIX + pc] = make_ulonglong2(pack2(ex[4*q]*inv,   ex[4*q+1]*inv),
                                                pack2(ex[4*q+2]*inv, ex[4*q+3]*inv));
    }
    __syncthreads();

    // ---- pass 1: offset 2, 16x16 interior, sB -> gmem direct ----
    if (tid < 256) {
        int ly = tid >> 4, lx = tid & 15;
        int pc = (2+ly)*REG + (2+lx);
        float4 wd = s_aff[pc];
        unsigned long long wx = pack2(wd.x, wd.x), wy = pack2(wd.y, wd.y);
        unsigned long long wz = pack2(wd.z, wd.z), ww = pack2(wd.w, wd.w);
        float ex[Kv]; float s = 0.f;
        #pragma unroll
        for (int q = 0; q < 8; q++) {
            const ulonglong2* r = sB + q*REGPIX + pc;
            ulonglong2 up = r[REG], dn = r[-REG], rt = r[1], lf = r[-1];
            unsigned long long a0 = mul2(wx, up.x);
            ffma2(a0, wy, dn.x); ffma2(a0, wz, rt.x); ffma2(a0, ww, lf.x);
            unsigned long long a1 = mul2(wx, up.y);
            ffma2(a1, wy, dn.y); ffma2(a1, wz, rt.y); ffma2(a1, ww, lf.y);
            float2 p0 = unpack2(a0), p1 = unpack2(a1);
            float e0 = __expf(p0.x), e1 = __expf(p0.y);
            float e2 = __expf(p1.x), e3 = __expf(p1.y);
            ex[4*q]=e0; ex[4*q+1]=e1; ex[4*q+2]=e2; ex[4*q+3]=e3;
            s += (e0 + e1) + (e2 + e3);
        }
        float inv = __fdividef(1.f, s);
        int gh = g0h + 2 + ly, gw = g0w + 2 + lx;
        float4* dst = (float4*)(Aout + (size_t)((b*Hv + gh)*Wv + gw)*Kv);
        #pragma unroll
        for (int g = 0; g < 8; g++)
            dst[g] = make_float4(ex[4*g]*inv, ex[4*g+1]*inv, ex[4*g+2]*inv, ex[4*g+3]*inv);
    }
}

// ============================================================================
// pooling stage 1
// ============================================================================
__global__ __launch_bounds__(256) void pool1_kernel(
    const float* __restrict__ A, const int* __restrict__ X, float* __restrict__ part)
{
    __shared__ int   s_x[Wv];
    __shared__ float s_red[3][8][Kv];
    __shared__ float s_cls[8][Kv][Cv];

    int bh = blockIdx.x; int b = bh >> 7, h = bh & 127;
    int tid = threadIdx.x;
    int k = tid & 31, wl = tid >> 5;

    if (tid < Wv) s_x[tid] = X[(b*Hv + h)*Wv + tid];
    __syncthreads();

    float mass = 0.f, wa = 0.f, w2a = 0.f;
    float cls[Cv];
    #pragma unroll
    for (int c = 0; c < Cv; c++) cls[c] = 0.f;

    #pragma unroll 1
    for (int it = 0; it < 16; it++) {
        int w = wl*16 + it;
        float a = A[((size_t)(b*Hv + h)*Wv + w)*Kv + k];
        float fw = (w + 0.5f) * (1.f/128.f);
        mass += a;
        wa  = fmaf(a, fw, wa);
        w2a = fmaf(a, fw*fw, w2a);
        int c = s_x[w];
        #pragma unroll
        for (int cc = 0; cc < Cv; cc++) cls[cc] += (c == cc) ? a : 0.f;
    }
    s_red[0][wl][k] = mass; s_red[1][wl][k] = wa; s_red[2][wl][k] = w2a;
    #pragma unroll
    for (int cc = 0; cc < Cv; cc++) s_cls[wl][k][cc] = cls[cc];
    __syncthreads();

    if (tid < Kv) {
        float m = 0.f, a1 = 0.f, a2 = 0.f, c10[Cv];
        #pragma unroll
        for (int cc = 0; cc < Cv; cc++) c10[cc] = 0.f;
        #pragma unroll
        for (int j = 0; j < 8; j++) {
            m  += s_red[0][j][tid];
            a1 += s_red[1][j][tid];
            a2 += s_red[2][j][tid];
            #pragma unroll
            for (int cc = 0; cc < Cv; cc++) c10[cc] += s_cls[j][tid][cc];
        }
        float* dst = part + ((size_t)(b*Hv + h)*Kv + tid)*13;
        dst[0] = m; dst[1] = a1; dst[2] = a2;
        #pragma unroll
        for (int cc = 0; cc < Cv; cc++) dst[3+cc] = c10[cc];
    }
}

// ============================================================================
// pooling stage 2
// ============================================================================
__global__ __launch_bounds__(256) void pool2_kernel(
    const float* __restrict__ part, float* __restrict__ T)
{
    int i = blockIdx.x*blockDim.x + threadIdx.x;
    if (i >= Bv*Kv) return;
    int b = i / Kv, k = i % Kv;

    float macc=0.f, ha=0.f, h2a=0.f, wa=0.f, w2a=0.f, cls[Cv];
    #pragma unroll
    for (int cc = 0; cc < Cv; cc++) cls[cc] = 0.f;

    for (int h = 0; h < Hv; h++) {
        const float* p = part + ((size_t)(b*Hv + h)*Kv + k)*13;
        float m = p[0];
        float fh = (h + 0.5f) * (1.f/128.f);
        macc += m;
        ha  = fmaf(m, fh, ha);
        h2a = fmaf(m, fh*fh, h2a);
        wa  += p[1];
        w2a += p[2];
        #pragma unroll
        for (int cc = 0; cc < Cv; cc++) cls[cc] += p[3+cc];
    }
    float mass = macc + 1e-6f;
    float inv = 1.f / mass;
    float h_c = ha*inv, w_c = wa*inv;
    float h2 = h2a*inv, w2 = w2a*inv;
    float h_sd = sqrtf(fmaxf(h2 - h_c*h_c, 0.f) + 1e-6f);
    float w_sd = sqrtf(fmaxf(w2 - w_c*w_c, 0.f) + 1e-6f);

    float* t = T + (size_t)i * T_FEATS;
    t[0] = mass * (1.f/16384.f);
    t[1] = h_c; t[2] = w_c;
    #pragma unroll
    for (int cc = 0; cc < Cv; cc++) t[3+cc] = cls[cc]*inv;
    t[13] = h_c - h_sd; t[14] = h_c + h_sd;
    t[15] = w_c - w_sd; t[16] = w_c + w_sd;
}

// ============================================================================
// launch
// ============================================================================
extern "C" void kernel_launch(void* const* d_in, const int* in_sizes, int n_in,
                              void* d_out, int out_size)
{
    const int*   X  = (const int*)  d_in[0];
    const float* w1 = (const float*)d_in[1];
    const float* b1 = (const float*)d_in[2];
    const float* w2 = (const float*)d_in[3];
    const float* b2 = (const float*)d_in[4];
    const float* w3 = (const float*)d_in[5];
    const float* b3 = (const float*)d_in[6];

    float* outA = (float*)d_out;
    float* outT = (float*)d_out + A_ELEMS;

    float *r1, *phi, *aff, *A0, *part;
    cudaGetSymbolAddress((void**)&r1,   g_r1);
    cudaGetSymbolAddress((void**)&phi,  g_phi);
    cudaGetSymbolAddress((void**)&aff,  g_aff);
    cudaGetSymbolAddress((void**)&A0,   g_A0);
    cudaGetSymbolAddress((void**)&part, g_part);

    cudaFuncSetAttribute(conv123_kernel,  cudaFuncAttributeMaxDynamicSharedMemorySize, CONV_SMEM);
    cudaFuncSetAttribute(msgpass2_kernel, cudaFuncAttributeMaxDynamicSharedMemorySize, MP2_SMEM);

    initA_kernel<<<Hv, 128>>>(A0);                                            // 0
    pad_kernel<<<1, 32>>>();                                                  // 1
    pad_kernel<<<1, 32>>>();                                                  // 2
    pad_kernel<<<1, 32>>>();                                                  // 3
    pad_kernel<<<1, 32>>>();                                                  // 4
    conv123_kernel<<<dim3(Bv, Hv/16, Wv/16), 256, CONV_SMEM>>>(
        X, w1, b1, w2, b2, w3, b3, phi);                                      // 5  <- ncu target
    aff_kernel<<<Bv*Hv, 128>>>(phi, aff);                                     // 6

    dim3 mpg(Wv/16, Hv/16, Bv);
    msgpass2_kernel<<<mpg, 512, MP2_SMEM>>>(A0,  0,         aff, r1);         // 7
    msgpass2_kernel<<<mpg, 512, MP2_SMEM>>>(r1,  Hv*Wv*Kv,  aff, phi);        // 8
    msgpass2_kernel<<<mpg, 512, MP2_SMEM>>>(phi, Hv*Wv*Kv,  aff, r1);         // 9
    msgpass2_kernel<<<mpg, 512, MP2_SMEM>>>(r1,  Hv*Wv*Kv,  aff, outA);       // 10

    pool1_kernel<<<Bv*Hv, 256>>>(outA, X, part);                              // 11
    pool2_kernel<<<4, 256>>>(part, outT);                                     // 12
}